// round 10
// baseline (speedup 1.0000x reference)
#include <cuda_runtime.h>
#include <cstdint>
#include <math.h>

#define DIM   768
#define HID   3072
#define HID2  1536
#define NLEV  9
#define SEQ   2048
#define MROWS 4096
#define EPSLN 1e-5f

#define BM 128
#define BN 128
#define BK 32
#define NT 256
#define MAX_TILES 48

#define ASTR 36                    /* A smem row stride in floats (144B) */
#define BSTR 136                   /* B smem row stride in floats (544B) */
#define A_FL (BM*ASTR)             /* 4608 floats = 18432 B */
#define B_FL (BK*BSTR)             /* 4352 floats = 17408 B */
#define A_BYTES (A_FL*4)
#define STAGE_FL (A_FL + B_FL)     /* 8960 floats */
#define STAGE_B (STAGE_FL*4)       /* 35840 B */
#define NSTAGE 3
#define SMEM_BYTES (NSTAGE*STAGE_B)   /* 107520 B */
#define CHUNK_BYTES 32768          /* A 16KB + B 16KB per chunk */

#define MID_MAIN_BLKS (6*32)
#define MID_BLKS (MID_MAIN_BLKS + 12*MAX_TILES)

// ---------------- scratch (no allocations allowed) ----------------
__device__ float g_xnorm[MROWS*DIM];
__device__ float g_h[(size_t)MROWS*HID];
__device__ float g_main[MROWS*DIM];
__device__ float g_hl[MROWS*HID2];
__device__ float g_W1r[DIM*HID];
__device__ float g_W2r[HID*DIM];
__device__ float g_A1r[NLEV*DIM*HID2];
__device__ float g_A2r[NLEV*HID2*DIM];
__device__ float g_mix[SEQ];
__device__ int   g_depth[SEQ];
__device__ int   g_rowperm[MROWS];
__device__ int   g_sched_lvl[MAX_TILES];
__device__ int   g_sched_start[MAX_TILES];
__device__ int   g_sched_rows[MAX_TILES];
__device__ int   g_ntiles;

// ---------------- PTX helpers ----------------
__device__ __forceinline__ uint32_t smem_u32(const void* p) {
    return (uint32_t)__cvta_generic_to_shared(p);
}
__device__ __forceinline__ uint32_t f2tf32(float x) {
    uint32_t r;
    asm("cvt.rna.tf32.f32 %0, %1;" : "=r"(r) : "f"(x));
    return r;
}
__device__ __forceinline__ float round_tf32f(float x) {
    return __uint_as_float(f2tf32(x));
}
__device__ __forceinline__ void ldsm_x4(uint32_t& r0, uint32_t& r1, uint32_t& r2, uint32_t& r3,
                                        uint32_t addr) {
    asm volatile("ldmatrix.sync.aligned.m8n8.x4.shared.b16 {%0,%1,%2,%3}, [%4];"
                 : "=r"(r0), "=r"(r1), "=r"(r2), "=r"(r3) : "r"(addr));
}
__device__ __forceinline__ void mma_tf32(float& c0, float& c1, float& c2, float& c3,
                                         uint32_t a0, uint32_t a1, uint32_t a2, uint32_t a3,
                                         uint32_t b0, uint32_t b1) {
    asm volatile(
        "mma.sync.aligned.m16n8k8.row.col.f32.tf32.tf32.f32 "
        "{%0,%1,%2,%3}, {%4,%5,%6,%7}, {%8,%9}, {%0,%1,%2,%3};"
        : "+f"(c0), "+f"(c1), "+f"(c2), "+f"(c3)
        : "r"(a0), "r"(a1), "r"(a2), "r"(a3), "r"(b0), "r"(b1));
}
__device__ __forceinline__ void bulk_g2s(uint32_t dst, const void* src, uint32_t bytes,
                                         uint32_t mbar) {
    asm volatile(
        "cp.async.bulk.shared::cta.global.mbarrier::complete_tx::bytes [%0], [%1], %2, [%3];"
        :: "r"(dst), "l"(src), "r"(bytes), "r"(mbar) : "memory");
}
__device__ __forceinline__ void mbar_init(uint32_t mbar, uint32_t cnt) {
    asm volatile("mbarrier.init.shared.b64 [%0], %1;" :: "r"(mbar), "r"(cnt) : "memory");
}
__device__ __forceinline__ void mbar_expect_tx(uint32_t mbar, uint32_t bytes) {
    asm volatile("mbarrier.arrive.expect_tx.shared.b64 _, [%0], %1;"
                 :: "r"(mbar), "r"(bytes) : "memory");
}
__device__ __forceinline__ void mbar_wait(uint32_t mbar, uint32_t parity) {
    uint32_t done;
    asm volatile(
        "{\n\t.reg .pred p;\n\t"
        "mbarrier.try_wait.parity.acquire.cta.shared::cta.b64 p, [%1], %2;\n\t"
        "selp.b32 %0, 1, 0, p;\n\t}"
        : "=r"(done) : "r"(mbar), "r"(parity) : "memory");
    if (!done) {
        asm volatile(
            "{\n\t.reg .pred P1;\n"
            "WL%=:\n\t"
            "mbarrier.try_wait.parity.acquire.cta.shared::cta.b64 P1, [%0], %1, 0x989680;\n\t"
            "@P1 bra WD%=;\n\t"
            "bra WL%=;\n"
            "WD%=:\n\t}"
            :: "r"(mbar), "r"(parity) : "memory");
    }
}

// ---------------- weight rounding: all four weight tensors in one launch ----------------
#define N4_W (DIM*HID/4)
#define N4_A (NLEV*DIM*HID2/4)
#define N4_TOTAL (2*N4_W + 2*N4_A)
__global__ void __launch_bounds__(256) round_all(const float4* __restrict__ W1,
                                                 const float4* __restrict__ W2,
                                                 const float4* __restrict__ A1,
                                                 const float4* __restrict__ A2) {
    int i = blockIdx.x*256 + threadIdx.x;
    if (i >= N4_TOTAL) return;
    const float4* src; float4* dst;
    if (i < N4_W)            { src = W1 + i;                dst = (float4*)g_W1r + i; }
    else if (i < 2*N4_W)     { src = W2 + (i - N4_W);       dst = (float4*)g_W2r + (i - N4_W); }
    else if (i < 2*N4_W+N4_A){ src = A1 + (i - 2*N4_W);     dst = (float4*)g_A1r + (i - 2*N4_W); }
    else                     { src = A2 + (i - 2*N4_W-N4_A);dst = (float4*)g_A2r + (i - 2*N4_W-N4_A); }
    float4 v = *src;
    v.x = round_tf32f(v.x); v.y = round_tf32f(v.y);
    v.z = round_tf32f(v.z); v.w = round_tf32f(v.w);
    *dst = v;
}

// ---------------- prep: depth clip, counting sort, tile schedule, mix ----------------
__global__ void prep_kernel(const int* __restrict__ levels, const float* __restrict__ lmw) {
    __shared__ int cnt[NLEV];
    __shared__ int cursor[NLEV];
    __shared__ float denom_sh;
    int t = threadIdx.x;
    if (t < NLEV) cnt[t] = 0;
    __syncthreads();
    for (int s = t; s < SEQ; s += NT) {
        int d = levels[s*4];
        d = min(max(d, 0), NLEV-1);
        g_depth[s] = d;
        atomicAdd(&cnt[d], 1);
    }
    __syncthreads();
    if (t == 0) {
        int o = 0, tile = 0;
        float denom = 0.f;
        for (int l = 0; l < NLEV; ++l) {
            cursor[l] = o;
            int rows = 2*cnt[l];
            int nt2 = (rows + BM - 1)/BM;
            for (int i = 0; i < nt2 && tile < MAX_TILES; ++i) {
                g_sched_lvl[tile]   = l;
                g_sched_start[tile] = o + i*BM;
                g_sched_rows[tile]  = min(BM, rows - i*BM);
                ++tile;
            }
            o += rows;
            denom += (float)cnt[l] * expf(lmw[l]);
        }
        for (int i = tile; i < MAX_TILES; ++i) g_sched_rows[i] = 0;
        g_ntiles = tile;
        denom_sh = denom;
    }
    __syncthreads();
    for (int r = t; r < MROWS; r += NT) {
        int s = r & (SEQ-1);
        int d = g_depth[s];
        int pos = atomicAdd(&cursor[d], 1);
        g_rowperm[pos] = r;
    }
    float denom = denom_sh;
    for (int s = t; s < SEQ; s += NT)
        g_mix[s] = expf(lmw[g_depth[s]]) / denom;
}

// ---------------- layernorm (writes tf32-rounded output) ----------------
__global__ void __launch_bounds__(256) ln_kernel(const float* __restrict__ x,
                                                 const float* __restrict__ gamma,
                                                 const float* __restrict__ beta) {
    int row = blockIdx.x;
    int t = threadIdx.x;
    const float* xr = x + (size_t)row*DIM;
    float v0 = xr[t], v1 = xr[t+256], v2 = xr[t+512];
    float s  = v0+v1+v2;
    float sq = v0*v0 + v1*v1 + v2*v2;
    __shared__ float red0[8], red1[8], mv[2];
#pragma unroll
    for (int o = 16; o > 0; o >>= 1) {
        s  += __shfl_xor_sync(0xffffffffu, s,  o);
        sq += __shfl_xor_sync(0xffffffffu, sq, o);
    }
    int wid = t >> 5, lid = t & 31;
    if (lid == 0) { red0[wid] = s; red1[wid] = sq; }
    __syncthreads();
    if (t == 0) {
        float S = 0.f, SQ = 0.f;
#pragma unroll
        for (int i = 0; i < 8; ++i) { S += red0[i]; SQ += red1[i]; }
        float mean = S * (1.0f/DIM);
        float var  = SQ * (1.0f/DIM) - mean*mean;
        mv[0] = mean; mv[1] = rsqrtf(var + EPSLN);
    }
    __syncthreads();
    float mean = mv[0], inv = mv[1];
    float* o = g_xnorm + (size_t)row*DIM;
    o[t]     = round_tf32f((v0-mean)*inv*gamma[t]     + beta[t]);
    o[t+256] = round_tf32f((v1-mean)*inv*gamma[t+256] + beta[t+256]);
    o[t+512] = round_tf32f((v2-mean)*inv*gamma[t+512] + beta[t+512]);
}

// ---------------- bulk chunk issue (warp 0 only): 128 A-row + 32 B-row copies ----------------
__device__ __forceinline__ void issue_chunk(const float* __restrict__ A, int lda,
                                            const float* __restrict__ B, int ldb,
                                            int n0, int k0, int stage,
                                            const int* __restrict__ rowidx,
                                            uint32_t sm_b, uint32_t mbar_b) {
    int lane = threadIdx.x & 31;
    uint32_t mbar = mbar_b + (uint32_t)(stage*8);
    if (lane == 0) mbar_expect_tx(mbar, CHUNK_BYTES);
    __syncwarp();
    uint32_t stA = sm_b + (uint32_t)(stage*STAGE_B);
#pragma unroll
    for (int i = 0; i < 4; ++i) {
        int row = lane + i*32;
        bulk_g2s(stA + (uint32_t)(row*(ASTR*4)),
                 A + (size_t)rowidx[row]*lda + k0, BK*4, mbar);
    }
    bulk_g2s(stA + (uint32_t)A_BYTES + (uint32_t)(lane*(BSTR*4)),
             B + (size_t)(k0+lane)*ldb + n0, BN*4, mbar);
}

// ---------------- mma mainloop: 3-stage bulk-async ring ----------------
__device__ __forceinline__ void mma_mainloop(const float* __restrict__ A, int lda,
                                             const float* __restrict__ B, int ldb,
                                             int K, int n0,
                                             const int* __restrict__ rowidx,
                                             float* smem, uint32_t mbar_b,
                                             float acc[4][4][4]) {
    int t = threadIdx.x;
    int wid = t >> 5, lane = t & 31;
    int wm = wid & 1, wn = wid >> 1;
    int qid = lane >> 2, qtr = lane & 3;

    // ldmatrix lane address pattern (per mt), byte offsets within A stage region
    int l8 = lane & 7, lhi = (lane >> 3) & 1, lk = lane >> 4;
    uint32_t a_off[4];
#pragma unroll
    for (int mt = 0; mt < 4; ++mt) {
        int row = wm*64 + mt*16 + lhi*8 + l8;
        a_off[mt] = (uint32_t)((row*ASTR + lk*4) * 4);
    }

    uint32_t sm_b = smem_u32(smem);
    int nch = K / BK;
    if (wid == 0) {
        issue_chunk(A, lda, B, ldb, n0, 0,  0, rowidx, sm_b, mbar_b);
        issue_chunk(A, lda, B, ldb, n0, BK, 1, rowidx, sm_b, mbar_b);
    }

    int s = 0, par = 0;
    for (int c = 0; c < nch; ++c) {
        mbar_wait(mbar_b + (uint32_t)(s*8), (uint32_t)par);
        uint32_t ab_base = sm_b + (uint32_t)(s*STAGE_B);
        const float* Bb = smem + s*STAGE_FL + A_FL;
#pragma unroll
        for (int ks = 0; ks < 4; ++ks) {
            int k0 = ks * 8;
            uint32_t af[4][4], bf[4][2];
#pragma unroll
            for (int mt = 0; mt < 4; ++mt)
                ldsm_x4(af[mt][0], af[mt][1], af[mt][2], af[mt][3],
                        ab_base + a_off[mt] + (uint32_t)(ks*32));
#pragma unroll
            for (int nt = 0; nt < 4; ++nt) {
                int cc = wn*32 + nt*8 + qid;
                bf[nt][0] = __float_as_uint(Bb[(k0 + qtr    )*BSTR + cc]);
                bf[nt][1] = __float_as_uint(Bb[(k0 + qtr + 4)*BSTR + cc]);
            }
#pragma unroll
            for (int mt = 0; mt < 4; ++mt)
#pragma unroll
                for (int nt = 0; nt < 4; ++nt)
                    mma_tf32(acc[mt][nt][0], acc[mt][nt][1],
                             acc[mt][nt][2], acc[mt][nt][3],
                             af[mt][0], af[mt][1], af[mt][2], af[mt][3],
                             bf[nt][0], bf[nt][1]);
        }
        __syncthreads();   // all warps done with stage s-1's successor reuse window
        if (wid == 0 && c + 2 < nch) {
            int s2 = s + 2; if (s2 >= NSTAGE) s2 -= NSTAGE;
            issue_chunk(A, lda, B, ldb, n0, (c+2)*BK, s2, rowidx, sm_b, mbar_b);
        }
        if (++s == NSTAGE) { s = 0; par ^= 1; }
    }
}

__device__ __forceinline__ float gelu_exact(float v) {
    return 0.5f * v * (1.0f + erff(v * 0.70710678118654752f));
}

#define KERNEL_SETUP()                                                       \
    extern __shared__ float smem[];                                          \
    __shared__ int s_row[BM];                                                \
    __shared__ __align__(8) uint64_t s_mbar[NSTAGE];                         \
    int t = threadIdx.x;                                                     \
    uint32_t mbar_b = smem_u32(s_mbar);                                      \
    if (t == 0) { mbar_init(mbar_b, 1); mbar_init(mbar_b+8, 1); mbar_init(mbar_b+16, 1); }

// ---------------- main MLP GEMM1: h = round(gelu(xnorm @ W1 + b1)) ----------------
__global__ void __launch_bounds__(NT, 2) k_gemm1_main(const float* __restrict__ b1) {
    KERNEL_SETUP();
    int m0 = blockIdx.y * BM, n0 = blockIdx.x * BN;
    if (t < BM) s_row[t] = m0 + t;
    __syncthreads();
    float acc[4][4][4] = {};
    mma_mainloop(g_xnorm, DIM, g_W1r, HID, DIM, n0, s_row, smem, mbar_b, acc);
    int wid = t >> 5, lane = t & 31;
    int wm = wid & 1, wn = wid >> 1, qid = lane >> 2, qtr = lane & 3;
#pragma unroll
    for (int mt = 0; mt < 4; ++mt) {
        int r0 = m0 + wm*64 + mt*16 + qid;
#pragma unroll
        for (int nt = 0; nt < 4; ++nt) {
            int col = n0 + wn*32 + nt*8 + qtr*2;
            float bx = b1[col], by = b1[col+1];
            *(float2*)(g_h + (size_t)r0*HID + col) =
                make_float2(round_tf32f(gelu_exact(acc[mt][nt][0]+bx)),
                            round_tf32f(gelu_exact(acc[mt][nt][1]+by)));
            *(float2*)(g_h + (size_t)(r0+8)*HID + col) =
                make_float2(round_tf32f(gelu_exact(acc[mt][nt][2]+bx)),
                            round_tf32f(gelu_exact(acc[mt][nt][3]+by)));
        }
    }
}

// ---------------- fused mid kernel: gemm2_main tiles + gemm1_adapt tiles ----------------
__global__ void __launch_bounds__(NT, 2) k_mid(const float* __restrict__ b2,
                                               const float* __restrict__ a1b) {
    KERNEL_SETUP();
    int bid = blockIdx.x;
    int wid = t >> 5, lane = t & 31;
    int wm = wid & 1, wn = wid >> 1, qid = lane >> 2, qtr = lane & 3;

    if (bid < MID_MAIN_BLKS) {
        int m0 = (bid / 6) * BM, n0 = (bid % 6) * BN;
        if (t < BM) s_row[t] = m0 + t;
        __syncthreads();
        float acc[4][4][4] = {};
        mma_mainloop(g_h, HID, g_W2r, DIM, HID, n0, s_row, smem, mbar_b, acc);
#pragma unroll
        for (int mt = 0; mt < 4; ++mt) {
            int r0 = m0 + wm*64 + mt*16 + qid;
#pragma unroll
            for (int nt = 0; nt < 4; ++nt) {
                int col = n0 + wn*32 + nt*8 + qtr*2;
                float bx = b2[col], by = b2[col+1];
                *(float2*)(g_main + (size_t)r0*DIM + col) =
                    make_float2(acc[mt][nt][0]+bx, acc[mt][nt][1]+by);
                *(float2*)(g_main + (size_t)(r0+8)*DIM + col) =
                    make_float2(acc[mt][nt][2]+bx, acc[mt][nt][3]+by);
            }
        }
    } else {
        int b2i = bid - MID_MAIN_BLKS;
        int tile = b2i / 12;
        if (tile >= g_ntiles) return;
        int n0 = (b2i % 12) * BN;
        int lvl = g_sched_lvl[tile], start = g_sched_start[tile], rows = g_sched_rows[tile];
        if (t < BM) s_row[t] = g_rowperm[start + min(t, rows-1)];
        __syncthreads();
        float acc[4][4][4] = {};
        mma_mainloop(g_xnorm, DIM, g_A1r + (size_t)lvl*DIM*HID2, HID2, DIM, n0,
                     s_row, smem, mbar_b, acc);
        const float* bb = a1b + (size_t)lvl*HID2;
#pragma unroll
        for (int mt = 0; mt < 4; ++mt) {
            int ml = wm*64 + mt*16 + qid;
#pragma unroll
            for (int nt = 0; nt < 4; ++nt) {
                int col = n0 + wn*32 + nt*8 + qtr*2;
                float bx = bb[col], by = bb[col+1];
                if (ml < rows)
                    *(float2*)(g_hl + (size_t)(start+ml)*HID2 + col) =
                        make_float2(round_tf32f(fmaxf(acc[mt][nt][0]+bx, 0.f)),
                                    round_tf32f(fmaxf(acc[mt][nt][1]+by, 0.f)));
                if (ml+8 < rows)
                    *(float2*)(g_hl + (size_t)(start+ml+8)*HID2 + col) =
                        make_float2(round_tf32f(fmaxf(acc[mt][nt][2]+bx, 0.f)),
                                    round_tf32f(fmaxf(acc[mt][nt][3]+by, 0.f)));
            }
        }
    }
}

// ---------------- adapter GEMM2 + final combine ----------------
__global__ void __launch_bounds__(NT, 2) k_gemm2_adapt(const float* __restrict__ a2b,
                                                       float* __restrict__ out) {
    if ((int)blockIdx.y >= g_ntiles) return;
    KERNEL_SETUP();
    int tile = blockIdx.y;
    int lvl = g_sched_lvl[tile], start = g_sched_start[tile], rows = g_sched_rows[tile];
    int n0 = blockIdx.x * BN;
    if (t < BM) s_row[t] = min(start + t, MROWS-1);   // g_hl rows are compacted
    __syncthreads();
    float acc[4][4][4] = {};
    mma_mainloop(g_hl, HID2, g_A2r + (size_t)lvl*HID2*DIM, DIM, HID2, n0, s_row,
                 smem, mbar_b, acc);
    int wid = t >> 5, lane = t & 31;
    int wm = wid & 1, wn = wid >> 1, qid = lane >> 2, qtr = lane & 3;
    const float* bb = a2b + (size_t)lvl*DIM;
#pragma unroll
    for (int mt = 0; mt < 4; ++mt) {
        int ml = wm*64 + mt*16 + qid;
#pragma unroll
        for (int nt = 0; nt < 4; ++nt) {
            int col = n0 + wn*32 + nt*8 + qtr*2;
            float bx = bb[col], by = bb[col+1];
            if (ml < rows) {
                int r = g_rowperm[start + ml];
                float mix = g_mix[r & (SEQ-1)];
                const float* mp = g_main + (size_t)r*DIM + col;
                *(float2*)(out + (size_t)r*DIM + col) =
                    make_float2(mp[0]*(1.f-mix) + (acc[mt][nt][0]+bx)*mix,
                                mp[1]*(1.f-mix) + (acc[mt][nt][1]+by)*mix);
            }
            if (ml+8 < rows) {
                int r = g_rowperm[start + ml + 8];
                float mix = g_mix[r & (SEQ-1)];
                const float* mp = g_main + (size_t)r*DIM + col;
                *(float2*)(out + (size_t)r*DIM + col) =
                    make_float2(mp[0]*(1.f-mix) + (acc[mt][nt][2]+bx)*mix,
                                mp[1]*(1.f-mix) + (acc[mt][nt][3]+by)*mix);
            }
        }
    }
}

// ---------------- launch ----------------
extern "C" void kernel_launch(void* const* d_in, const int* in_sizes, int n_in,
                              void* d_out, int out_size) {
    const float* x      = (const float*)d_in[0];
    const int*   levels = (const int*)  d_in[1];
    const float* gamma  = (const float*)d_in[2];
    const float* beta   = (const float*)d_in[3];
    const float* W1     = (const float*)d_in[4];
    const float* b1     = (const float*)d_in[5];
    const float* W2     = (const float*)d_in[6];
    const float* b2     = (const float*)d_in[7];
    const float* A1     = (const float*)d_in[8];
    const float* a1b    = (const float*)d_in[9];
    const float* A2     = (const float*)d_in[10];
    const float* a2b    = (const float*)d_in[11];
    const float* lmw    = (const float*)d_in[12];
    float* out = (float*)d_out;

    cudaFuncSetAttribute(k_gemm1_main,  cudaFuncAttributeMaxDynamicSharedMemorySize, SMEM_BYTES);
    cudaFuncSetAttribute(k_mid,         cudaFuncAttributeMaxDynamicSharedMemorySize, SMEM_BYTES);
    cudaFuncSetAttribute(k_gemm2_adapt, cudaFuncAttributeMaxDynamicSharedMemorySize, SMEM_BYTES);

    round_all<<<(N4_TOTAL+255)/256, 256>>>((const float4*)W1, (const float4*)W2,
                                           (const float4*)A1, (const float4*)A2);
    prep_kernel<<<1, NT>>>(levels, lmw);
    ln_kernel<<<MROWS, 256>>>(x, gamma, beta);
    k_gemm1_main <<<dim3(HID/BN, MROWS/BM), NT, SMEM_BYTES>>>(b1);
    k_mid        <<<MID_BLKS, NT, SMEM_BYTES>>>(b2, a1b);
    k_gemm2_adapt<<<dim3(DIM/BN, MAX_TILES), NT, SMEM_BYTES>>>(a2b, out);
}

// round 11
// speedup vs baseline: 2.7459x; 2.7459x over previous
#include <cuda_runtime.h>
#include <cstdint>
#include <math.h>

#define DIM   768
#define HID   3072
#define HID2  1536
#define NLEV  9
#define SEQ   2048
#define MROWS 4096
#define EPSLN 1e-5f

#define BM 256
#define BN 128
#define BK 32
#define NT 512
#define MAX_TILES 28

#define ASTR 36    /* A smem row stride in floats (144B): bank-bijective, 16B aligned */
#define BSTR 136   /* B smem row stride in floats (544B) */
#define ABUF (BM*ASTR)   /* 9216 floats */
#define BBUF (BK*BSTR)   /* 4352 floats */
#define STAGE (ABUF+BBUF)          /* 13568 floats = 54272 B */
#define NSTAGE 3
#define SMEM_BYTES (NSTAGE*STAGE*4)   /* 162816 B */

#define MID_MAIN_BLKS (6*16)   /* gemm2_main tiles: 6 n x 16 m */
#define MID_BLKS (MID_MAIN_BLKS + 12*MAX_TILES)

// ---------------- scratch (no allocations allowed) ----------------
__device__ float g_xnorm[MROWS*DIM];
__device__ float g_h[(size_t)MROWS*HID];
__device__ float g_main[MROWS*DIM];
__device__ float g_hl[MROWS*HID2];
__device__ float g_W1r[DIM*HID];
__device__ float g_W2r[HID*DIM];
__device__ float g_A1r[NLEV*DIM*HID2];
__device__ float g_A2r[NLEV*HID2*DIM];
__device__ float g_mix[SEQ];
__device__ int   g_depth[SEQ];
__device__ int   g_rowperm[MROWS];
__device__ int   g_sched_lvl[MAX_TILES];
__device__ int   g_sched_start[MAX_TILES];
__device__ int   g_sched_rows[MAX_TILES];
__device__ int   g_ntiles;

// ---------------- PTX helpers ----------------
__device__ __forceinline__ uint32_t smem_u32(const void* p) {
    return (uint32_t)__cvta_generic_to_shared(p);
}
__device__ __forceinline__ void cp16(uint32_t dst, const void* src) {
    asm volatile("cp.async.cg.shared.global [%0], [%1], 16;" :: "r"(dst), "l"(src));
}
__device__ __forceinline__ void cp_commit() {
    asm volatile("cp.async.commit_group;" ::: "memory");
}
__device__ __forceinline__ void cp_wait1() {
    asm volatile("cp.async.wait_group 1;" ::: "memory");
}
__device__ __forceinline__ uint32_t f2tf32(float x) {
    uint32_t r;
    asm("cvt.rna.tf32.f32 %0, %1;" : "=r"(r) : "f"(x));
    return r;
}
__device__ __forceinline__ float round_tf32f(float x) {
    return __uint_as_float(f2tf32(x));
}
__device__ __forceinline__ void ldsm_x4(uint32_t& r0, uint32_t& r1, uint32_t& r2, uint32_t& r3,
                                        uint32_t addr) {
    asm volatile("ldmatrix.sync.aligned.m8n8.x4.shared.b16 {%0,%1,%2,%3}, [%4];"
                 : "=r"(r0), "=r"(r1), "=r"(r2), "=r"(r3) : "r"(addr));
}
__device__ __forceinline__ void mma_tf32(float& c0, float& c1, float& c2, float& c3,
                                         uint32_t a0, uint32_t a1, uint32_t a2, uint32_t a3,
                                         uint32_t b0, uint32_t b1) {
    asm volatile(
        "mma.sync.aligned.m16n8k8.row.col.f32.tf32.tf32.f32 "
        "{%0,%1,%2,%3}, {%4,%5,%6,%7}, {%8,%9}, {%0,%1,%2,%3};"
        : "+f"(c0), "+f"(c1), "+f"(c2), "+f"(c3)
        : "r"(a0), "r"(a1), "r"(a2), "r"(a3), "r"(b0), "r"(b1));
}

// ---------------- weight rounding: all four weight tensors in one launch ----------------
#define N4_W (DIM*HID/4)
#define N4_A (NLEV*DIM*HID2/4)
#define N4_TOTAL (2*N4_W + 2*N4_A)
__global__ void __launch_bounds__(256) round_all(const float4* __restrict__ W1,
                                                 const float4* __restrict__ W2,
                                                 const float4* __restrict__ A1,
                                                 const float4* __restrict__ A2) {
    int i = blockIdx.x*256 + threadIdx.x;
    if (i >= N4_TOTAL) return;
    const float4* src; float4* dst;
    if (i < N4_W)            { src = W1 + i;                dst = (float4*)g_W1r + i; }
    else if (i < 2*N4_W)     { src = W2 + (i - N4_W);       dst = (float4*)g_W2r + (i - N4_W); }
    else if (i < 2*N4_W+N4_A){ src = A1 + (i - 2*N4_W);     dst = (float4*)g_A1r + (i - 2*N4_W); }
    else                     { src = A2 + (i - 2*N4_W-N4_A);dst = (float4*)g_A2r + (i - 2*N4_W-N4_A); }
    float4 v = *src;
    v.x = round_tf32f(v.x); v.y = round_tf32f(v.y);
    v.z = round_tf32f(v.z); v.w = round_tf32f(v.w);
    *dst = v;
}

// ---------------- prep: depth clip, counting sort, tile schedule (256-row tiles), mix ----------------
__global__ void prep_kernel(const int* __restrict__ levels, const float* __restrict__ lmw) {
    __shared__ int cnt[NLEV];
    __shared__ int cursor[NLEV];
    __shared__ float denom_sh;
    int t = threadIdx.x;
    if (t < NLEV) cnt[t] = 0;
    __syncthreads();
    for (int s = t; s < SEQ; s += 256) {
        int d = levels[s*4];
        d = min(max(d, 0), NLEV-1);
        g_depth[s] = d;
        atomicAdd(&cnt[d], 1);
    }
    __syncthreads();
    if (t == 0) {
        int o = 0, tile = 0;
        float denom = 0.f;
        for (int l = 0; l < NLEV; ++l) {
            cursor[l] = o;
            int rows = 2*cnt[l];
            int nt2 = (rows + BM - 1)/BM;
            for (int i = 0; i < nt2 && tile < MAX_TILES; ++i) {
                g_sched_lvl[tile]   = l;
                g_sched_start[tile] = o + i*BM;
                g_sched_rows[tile]  = min(BM, rows - i*BM);
                ++tile;
            }
            o += rows;
            denom += (float)cnt[l] * expf(lmw[l]);
        }
        for (int i = tile; i < MAX_TILES; ++i) g_sched_rows[i] = 0;
        g_ntiles = tile;
        denom_sh = denom;
    }
    __syncthreads();
    for (int r = t; r < MROWS; r += 256) {
        int s = r & (SEQ-1);
        int d = g_depth[s];
        int pos = atomicAdd(&cursor[d], 1);
        g_rowperm[pos] = r;
    }
    float denom = denom_sh;
    for (int s = t; s < SEQ; s += 256)
        g_mix[s] = expf(lmw[g_depth[s]]) / denom;
}

// ---------------- layernorm (writes tf32-rounded output) ----------------
__global__ void __launch_bounds__(256) ln_kernel(const float* __restrict__ x,
                                                 const float* __restrict__ gamma,
                                                 const float* __restrict__ beta) {
    int row = blockIdx.x;
    int t = threadIdx.x;
    const float* xr = x + (size_t)row*DIM;
    float v0 = xr[t], v1 = xr[t+256], v2 = xr[t+512];
    float s  = v0+v1+v2;
    float sq = v0*v0 + v1*v1 + v2*v2;
    __shared__ float red0[8], red1[8], mv[2];
#pragma unroll
    for (int o = 16; o > 0; o >>= 1) {
        s  += __shfl_xor_sync(0xffffffffu, s,  o);
        sq += __shfl_xor_sync(0xffffffffu, sq, o);
    }
    int wid = t >> 5, lid = t & 31;
    if (lid == 0) { red0[wid] = s; red1[wid] = sq; }
    __syncthreads();
    if (t == 0) {
        float S = 0.f, SQ = 0.f;
#pragma unroll
        for (int i = 0; i < 8; ++i) { S += red0[i]; SQ += red1[i]; }
        float mean = S * (1.0f/DIM);
        float var  = SQ * (1.0f/DIM) - mean*mean;
        mv[0] = mean; mv[1] = rsqrtf(var + EPSLN);
    }
    __syncthreads();
    float mean = mv[0], inv = mv[1];
    float* o = g_xnorm + (size_t)row*DIM;
    o[t]     = round_tf32f((v0-mean)*inv*gamma[t]     + beta[t]);
    o[t+256] = round_tf32f((v1-mean)*inv*gamma[t+256] + beta[t+256]);
    o[t+512] = round_tf32f((v2-mean)*inv*gamma[t+512] + beta[t+512]);
}

// ---------------- chunk loader: A 256 rows (gathered), B 32x128; NT=512 ----------------
__device__ __forceinline__ void load_chunk(const float* __restrict__ A, int lda,
                                           const float* __restrict__ B, int ldb,
                                           int n0, int k0,
                                           const int* __restrict__ rowidx,
                                           float* As, float* Bs) {
    int t = threadIdx.x;
#pragma unroll
    for (int i = 0; i < 4; ++i) {
        int ci = t + i*NT;
        int row = ci >> 3, seg = ci & 7;
        cp16(smem_u32(As + row*ASTR + seg*4),
             A + (size_t)rowidx[row]*lda + k0 + seg*4);
    }
#pragma unroll
    for (int i = 0; i < 2; ++i) {
        int ci = t + i*NT;
        int k = ci >> 5, ns = ci & 31;
        cp16(smem_u32(Bs + k*BSTR + ns*4),
             B + (size_t)(k0+k)*ldb + n0 + ns*4);
    }
}

// ---------------- mma mainloop: 3-stage ring; 16 warps 8(M)x2(N), 32x64 each ----------------
__device__ __forceinline__ void mma_mainloop(const float* __restrict__ A, int lda,
                                             const float* __restrict__ B, int ldb,
                                             int K, int n0,
                                             const int* __restrict__ rowidx,
                                             float* smem, float acc[2][8][4]) {
    int t = threadIdx.x;
    int wid = t >> 5, lane = t & 31;
    int wm = wid >> 1, wn = wid & 1;
    int qid = lane >> 2, qtr = lane & 3;

    // ldmatrix lane address pattern (per mt), byte offsets within A stage
    int l8 = lane & 7, lhi = (lane >> 3) & 1, lk = lane >> 4;
    uint32_t a_off[2];
#pragma unroll
    for (int mt = 0; mt < 2; ++mt) {
        int row = wm*32 + mt*16 + lhi*8 + l8;
        a_off[mt] = (uint32_t)((row*ASTR + lk*4) * 4);
    }

    int nch = K / BK;
    load_chunk(A, lda, B, ldb, n0, 0,  rowidx, smem,           smem + ABUF);
    cp_commit();
    load_chunk(A, lda, B, ldb, n0, BK, rowidx, smem + STAGE,   smem + STAGE + ABUF);
    cp_commit();

    for (int c = 0; c < nch; ++c) {
        cp_wait1();
        __syncthreads();
        const float* Bb = smem + (c % NSTAGE)*STAGE + ABUF;
        uint32_t ab_base = smem_u32(smem + (c % NSTAGE)*STAGE);
#pragma unroll
        for (int ks = 0; ks < 4; ++ks) {
            int k0 = ks * 8;
            uint32_t af[2][4], bf[8][2];
#pragma unroll
            for (int mt = 0; mt < 2; ++mt)
                ldsm_x4(af[mt][0], af[mt][1], af[mt][2], af[mt][3],
                        ab_base + a_off[mt] + (uint32_t)(ks*32));
#pragma unroll
            for (int nt = 0; nt < 8; ++nt) {
                int cc = wn*64 + nt*8 + qid;
                bf[nt][0] = __float_as_uint(Bb[(k0 + qtr    )*BSTR + cc]);
                bf[nt][1] = __float_as_uint(Bb[(k0 + qtr + 4)*BSTR + cc]);
            }
#pragma unroll
            for (int mt = 0; mt < 2; ++mt)
#pragma unroll
                for (int nt = 0; nt < 8; ++nt)
                    mma_tf32(acc[mt][nt][0], acc[mt][nt][1],
                             acc[mt][nt][2], acc[mt][nt][3],
                             af[mt][0], af[mt][1], af[mt][2], af[mt][3],
                             bf[nt][0], bf[nt][1]);
        }
        if (c + 2 < nch) {
            int st = (c + 2) % NSTAGE;
            load_chunk(A, lda, B, ldb, n0, (c+2)*BK, rowidx,
                       smem + st*STAGE, smem + st*STAGE + ABUF);
        }
        cp_commit();   // uniform group count (empty at tail)
    }
}

__device__ __forceinline__ float gelu_exact(float v) {
    return 0.5f * v * (1.0f + erff(v * 0.70710678118654752f));
}

// ---------------- main MLP GEMM1: h = round(gelu(xnorm @ W1 + b1)) ----------------
__global__ void __launch_bounds__(NT, 1) k_gemm1_main(const float* __restrict__ b1) {
    extern __shared__ float smem[];
    __shared__ int s_row[BM];
    int t = threadIdx.x;
    int m0 = blockIdx.y * BM, n0 = blockIdx.x * BN;
    if (t < BM) s_row[t] = m0 + t;
    __syncthreads();
    float acc[2][8][4] = {};
    mma_mainloop(g_xnorm, DIM, g_W1r, HID, DIM, n0, s_row, smem, acc);
    int wid = t >> 5, lane = t & 31;
    int wm = wid >> 1, wn = wid & 1, qid = lane >> 2, qtr = lane & 3;
#pragma unroll
    for (int mt = 0; mt < 2; ++mt) {
        int r0 = m0 + wm*32 + mt*16 + qid;
#pragma unroll
        for (int nt = 0; nt < 8; ++nt) {
            int col = n0 + wn*64 + nt*8 + qtr*2;
            float bx = b1[col], by = b1[col+1];
            *(float2*)(g_h + (size_t)r0*HID + col) =
                make_float2(round_tf32f(gelu_exact(acc[mt][nt][0]+bx)),
                            round_tf32f(gelu_exact(acc[mt][nt][1]+by)));
            *(float2*)(g_h + (size_t)(r0+8)*HID + col) =
                make_float2(round_tf32f(gelu_exact(acc[mt][nt][2]+bx)),
                            round_tf32f(gelu_exact(acc[mt][nt][3]+by)));
        }
    }
}

// ---------------- fused mid kernel: gemm2_main tiles + gemm1_adapt tiles ----------------
__global__ void __launch_bounds__(NT, 1) k_mid(const float* __restrict__ b2,
                                               const float* __restrict__ a1b) {
    extern __shared__ float smem[];
    __shared__ int s_row[BM];
    int t = threadIdx.x;
    int bid = blockIdx.x;
    int wid = t >> 5, lane = t & 31;
    int wm = wid >> 1, wn = wid & 1, qid = lane >> 2, qtr = lane & 3;

    if (bid < MID_MAIN_BLKS) {
        // ---- main = g_h @ W2r + b2 ----
        int m0 = (bid / 6) * BM, n0 = (bid % 6) * BN;
        if (t < BM) s_row[t] = m0 + t;
        __syncthreads();
        float acc[2][8][4] = {};
        mma_mainloop(g_h, HID, g_W2r, DIM, HID, n0, s_row, smem, acc);
#pragma unroll
        for (int mt = 0; mt < 2; ++mt) {
            int r0 = m0 + wm*32 + mt*16 + qid;
#pragma unroll
            for (int nt = 0; nt < 8; ++nt) {
                int col = n0 + wn*64 + nt*8 + qtr*2;
                float bx = b2[col], by = b2[col+1];
                *(float2*)(g_main + (size_t)r0*DIM + col) =
                    make_float2(acc[mt][nt][0]+bx, acc[mt][nt][1]+by);
                *(float2*)(g_main + (size_t)(r0+8)*DIM + col) =
                    make_float2(acc[mt][nt][2]+bx, acc[mt][nt][3]+by);
            }
        }
    } else {
        // ---- hl = round(relu(xnorm[perm] @ A1r[lvl] + a1b[lvl])) ----
        int b2i = bid - MID_MAIN_BLKS;
        int tile = b2i / 12;
        if (tile >= g_ntiles) return;
        int n0 = (b2i % 12) * BN;
        int lvl = g_sched_lvl[tile], start = g_sched_start[tile], rows = g_sched_rows[tile];
        if (t < BM) s_row[t] = g_rowperm[start + min(t, rows-1)];
        __syncthreads();
        float acc[2][8][4] = {};
        mma_mainloop(g_xnorm, DIM, g_A1r + (size_t)lvl*DIM*HID2, HID2, DIM, n0,
                     s_row, smem, acc);
        const float* bb = a1b + (size_t)lvl*HID2;
#pragma unroll
        for (int mt = 0; mt < 2; ++mt) {
            int ml = wm*32 + mt*16 + qid;
#pragma unroll
            for (int nt = 0; nt < 8; ++nt) {
                int col = n0 + wn*64 + nt*8 + qtr*2;
                float bx = bb[col], by = bb[col+1];
                if (ml < rows)
                    *(float2*)(g_hl + (size_t)(start+ml)*HID2 + col) =
                        make_float2(round_tf32f(fmaxf(acc[mt][nt][0]+bx, 0.f)),
                                    round_tf32f(fmaxf(acc[mt][nt][1]+by, 0.f)));
                if (ml+8 < rows)
                    *(float2*)(g_hl + (size_t)(start+ml+8)*HID2 + col) =
                        make_float2(round_tf32f(fmaxf(acc[mt][nt][2]+bx, 0.f)),
                                    round_tf32f(fmaxf(acc[mt][nt][3]+by, 0.f)));
            }
        }
    }
}

// ---------------- adapter GEMM2 + final combine ----------------
__global__ void __launch_bounds__(NT, 1) k_gemm2_adapt(const float* __restrict__ a2b,
                                                       float* __restrict__ out) {
    if ((int)blockIdx.y >= g_ntiles) return;
    extern __shared__ float smem[];
    __shared__ int s_row[BM];
    int t = threadIdx.x;
    int tile = blockIdx.y;
    int lvl = g_sched_lvl[tile], start = g_sched_start[tile], rows = g_sched_rows[tile];
    int n0 = blockIdx.x * BN;
    if (t < BM) s_row[t] = min(start + t, MROWS-1);   // g_hl rows are compacted
    __syncthreads();
    float acc[2][8][4] = {};
    mma_mainloop(g_hl, HID2, g_A2r + (size_t)lvl*HID2*DIM, DIM, HID2, n0, s_row, smem, acc);
    int wid = t >> 5, lane = t & 31;
    int wm = wid >> 1, wn = wid & 1, qid = lane >> 2, qtr = lane & 3;
    const float* bb = a2b + (size_t)lvl*DIM;
#pragma unroll
    for (int mt = 0; mt < 2; ++mt) {
        int ml = wm*32 + mt*16 + qid;
#pragma unroll
        for (int nt = 0; nt < 8; ++nt) {
            int col = n0 + wn*64 + nt*8 + qtr*2;
            float bx = bb[col], by = bb[col+1];
            if (ml < rows) {
                int r = g_rowperm[start + ml];
                float mix = g_mix[r & (SEQ-1)];
                const float* mp = g_main + (size_t)r*DIM + col;
                *(float2*)(out + (size_t)r*DIM + col) =
                    make_float2(mp[0]*(1.f-mix) + (acc[mt][nt][0]+bx)*mix,
                                mp[1]*(1.f-mix) + (acc[mt][nt][1]+by)*mix);
            }
            if (ml+8 < rows) {
                int r = g_rowperm[start + ml + 8];
                float mix = g_mix[r & (SEQ-1)];
                const float* mp = g_main + (size_t)r*DIM + col;
                *(float2*)(out + (size_t)r*DIM + col) =
                    make_float2(mp[0]*(1.f-mix) + (acc[mt][nt][2]+bx)*mix,
                                mp[1]*(1.f-mix) + (acc[mt][nt][3]+by)*mix);
            }
        }
    }
}

// ---------------- launch ----------------
extern "C" void kernel_launch(void* const* d_in, const int* in_sizes, int n_in,
                              void* d_out, int out_size) {
    const float* x      = (const float*)d_in[0];
    const int*   levels = (const int*)  d_in[1];
    const float* gamma  = (const float*)d_in[2];
    const float* beta   = (const float*)d_in[3];
    const float* W1     = (const float*)d_in[4];
    const float* b1     = (const float*)d_in[5];
    const float* W2     = (const float*)d_in[6];
    const float* b2     = (const float*)d_in[7];
    const float* A1     = (const float*)d_in[8];
    const float* a1b    = (const float*)d_in[9];
    const float* A2     = (const float*)d_in[10];
    const float* a2b    = (const float*)d_in[11];
    const float* lmw    = (const float*)d_in[12];
    float* out = (float*)d_out;

    cudaFuncSetAttribute(k_gemm1_main,  cudaFuncAttributeMaxDynamicSharedMemorySize, SMEM_BYTES);
    cudaFuncSetAttribute(k_mid,         cudaFuncAttributeMaxDynamicSharedMemorySize, SMEM_BYTES);
    cudaFuncSetAttribute(k_gemm2_adapt, cudaFuncAttributeMaxDynamicSharedMemorySize, SMEM_BYTES);

    round_all<<<(N4_TOTAL+255)/256, 256>>>((const float4*)W1, (const float4*)W2,
                                           (const float4*)A1, (const float4*)A2);
    prep_kernel<<<1, 256>>>(levels, lmw);
    ln_kernel<<<MROWS, 256>>>(x, gamma, beta);
    k_gemm1_main <<<dim3(HID/BN, MROWS/BM), NT, SMEM_BYTES>>>(b1);
    k_mid        <<<MID_BLKS, NT, SMEM_BYTES>>>(b2, a1b);
    k_gemm2_adapt<<<dim3(DIM/BN, MAX_TILES), NT, SMEM_BYTES>>>(a2b, out);
}

// round 12
// speedup vs baseline: 2.8544x; 1.0395x over previous
#include <cuda_runtime.h>
#include <cstdint>
#include <math.h>

#define DIM   768
#define HID   3072
#define HID2  1536
#define NLEV  9
#define SEQ   2048
#define MROWS 4096
#define EPSLN 1e-5f

#define BM 128
#define BN 96
#define BK 32
#define NT 384
#define MAX_TILES 48

#define ASTR 36    /* A smem row stride in floats (144B): bank-bijective, 16B aligned */
#define BSTR 104   /* B smem row stride in floats (96 data + 8 pad) */
#define ABUF (BM*ASTR)   /* 4608 floats */
#define BBUF (BK*BSTR)   /* 3328 floats */
#define STAGE (ABUF+BBUF)          /* 7936 floats = 31744 B */
#define NSTAGE 3
#define SMEM_BYTES (NSTAGE*STAGE*4)   /* 95232 B */

#define NMAIN (HID/BN)    /* 32 */
#define NDIM  (DIM/BN)    /* 8 */
#define NH2   (HID2/BN)   /* 16 */
#define MID_MAIN_BLKS (NDIM*32)   /* 256 */
#define MID_BLKS (MID_MAIN_BLKS + NH2*MAX_TILES)   /* 256+768=1024 */

// ---------------- scratch (no allocations allowed) ----------------
__device__ float g_xnorm[MROWS*DIM];
__device__ float g_h[(size_t)MROWS*HID];
__device__ float g_main[MROWS*DIM];
__device__ float g_hl[MROWS*HID2];
__device__ float g_W1r[DIM*HID];
__device__ float g_W2r[HID*DIM];
__device__ float g_A1r[NLEV*DIM*HID2];
__device__ float g_A2r[NLEV*HID2*DIM];
__device__ float g_mix[SEQ];
__device__ int   g_depth[SEQ];
__device__ int   g_rowperm[MROWS];
__device__ int   g_sched_lvl[MAX_TILES];
__device__ int   g_sched_start[MAX_TILES];
__device__ int   g_sched_rows[MAX_TILES];
__device__ int   g_ntiles;

// ---------------- PTX helpers ----------------
__device__ __forceinline__ uint32_t smem_u32(const void* p) {
    return (uint32_t)__cvta_generic_to_shared(p);
}
__device__ __forceinline__ void cp16(uint32_t dst, const void* src) {
    asm volatile("cp.async.cg.shared.global [%0], [%1], 16;" :: "r"(dst), "l"(src));
}
__device__ __forceinline__ void cp_commit() {
    asm volatile("cp.async.commit_group;" ::: "memory");
}
__device__ __forceinline__ void cp_wait1() {
    asm volatile("cp.async.wait_group 1;" ::: "memory");
}
__device__ __forceinline__ uint32_t f2tf32(float x) {
    uint32_t r;
    asm("cvt.rna.tf32.f32 %0, %1;" : "=r"(r) : "f"(x));
    return r;
}
__device__ __forceinline__ float round_tf32f(float x) {
    return __uint_as_float(f2tf32(x));
}
__device__ __forceinline__ void ldsm_x4(uint32_t& r0, uint32_t& r1, uint32_t& r2, uint32_t& r3,
                                        uint32_t addr) {
    asm volatile("ldmatrix.sync.aligned.m8n8.x4.shared.b16 {%0,%1,%2,%3}, [%4];"
                 : "=r"(r0), "=r"(r1), "=r"(r2), "=r"(r3) : "r"(addr));
}
__device__ __forceinline__ void mma_tf32(float& c0, float& c1, float& c2, float& c3,
                                         uint32_t a0, uint32_t a1, uint32_t a2, uint32_t a3,
                                         uint32_t b0, uint32_t b1) {
    asm volatile(
        "mma.sync.aligned.m16n8k8.row.col.f32.tf32.tf32.f32 "
        "{%0,%1,%2,%3}, {%4,%5,%6,%7}, {%8,%9}, {%0,%1,%2,%3};"
        : "+f"(c0), "+f"(c1), "+f"(c2), "+f"(c3)
        : "r"(a0), "r"(a1), "r"(a2), "r"(a3), "r"(b0), "r"(b1));
}

// ---------------- fused prep: weight rounding + schedule + layernorm, one launch ----------------
#define N4_W (DIM*HID/4)
#define N4_A (NLEV*DIM*HID2/4)
#define N4_TOTAL (2*N4_W + 2*N4_A)
#define NB_ROUND ((N4_TOTAL+255)/256)   /* 10368 */
#define NB_PREP_ALL (NB_ROUND + 1 + MROWS)

__global__ void __launch_bounds__(256) k_prep_all(
        const float4* __restrict__ W1, const float4* __restrict__ W2,
        const float4* __restrict__ A1, const float4* __restrict__ A2,
        const int* __restrict__ levels, const float* __restrict__ lmw,
        const float* __restrict__ x, const float* __restrict__ gamma,
        const float* __restrict__ beta) {
    int b = blockIdx.x;
    int t = threadIdx.x;
    if (b < NB_ROUND) {
        // ---- weight tf32 rounding ----
        int i = b*256 + t;
        if (i >= N4_TOTAL) return;
        const float4* src; float4* dst;
        if (i < N4_W)            { src = W1 + i;                dst = (float4*)g_W1r + i; }
        else if (i < 2*N4_W)     { src = W2 + (i - N4_W);       dst = (float4*)g_W2r + (i - N4_W); }
        else if (i < 2*N4_W+N4_A){ src = A1 + (i - 2*N4_W);     dst = (float4*)g_A1r + (i - 2*N4_W); }
        else                     { src = A2 + (i - 2*N4_W-N4_A);dst = (float4*)g_A2r + (i - 2*N4_W-N4_A); }
        float4 v = *src;
        v.x = round_tf32f(v.x); v.y = round_tf32f(v.y);
        v.z = round_tf32f(v.z); v.w = round_tf32f(v.w);
        *dst = v;
    } else if (b == NB_ROUND) {
        // ---- depth clip, counting sort, tile schedule, mix ----
        __shared__ int cnt[NLEV];
        __shared__ int cursor[NLEV];
        __shared__ float denom_sh;
        if (t < NLEV) cnt[t] = 0;
        __syncthreads();
        for (int s = t; s < SEQ; s += 256) {
            int d = levels[s*4];
            d = min(max(d, 0), NLEV-1);
            g_depth[s] = d;
            atomicAdd(&cnt[d], 1);
        }
        __syncthreads();
        if (t == 0) {
            int o = 0, tile = 0;
            float denom = 0.f;
            for (int l = 0; l < NLEV; ++l) {
                cursor[l] = o;
                int rows = 2*cnt[l];
                int nt2 = (rows + BM - 1)/BM;
                for (int i = 0; i < nt2 && tile < MAX_TILES; ++i) {
                    g_sched_lvl[tile]   = l;
                    g_sched_start[tile] = o + i*BM;
                    g_sched_rows[tile]  = min(BM, rows - i*BM);
                    ++tile;
                }
                o += rows;
                denom += (float)cnt[l] * expf(lmw[l]);
            }
            for (int i = tile; i < MAX_TILES; ++i) g_sched_rows[i] = 0;
            g_ntiles = tile;
            denom_sh = denom;
        }
        __syncthreads();
        for (int r = t; r < MROWS; r += 256) {
            int s = r & (SEQ-1);
            int d = g_depth[s];
            int pos = atomicAdd(&cursor[d], 1);
            g_rowperm[pos] = r;
        }
        float denom = denom_sh;
        for (int s = t; s < SEQ; s += 256)
            g_mix[s] = expf(lmw[g_depth[s]]) / denom;
    } else {
        // ---- layernorm row, tf32-rounded output ----
        int row = b - NB_ROUND - 1;
        const float* xr = x + (size_t)row*DIM;
        float v0 = xr[t], v1 = xr[t+256], v2 = xr[t+512];
        float s  = v0+v1+v2;
        float sq = v0*v0 + v1*v1 + v2*v2;
        __shared__ float red0[8], red1[8], mv[2];
#pragma unroll
        for (int o = 16; o > 0; o >>= 1) {
            s  += __shfl_xor_sync(0xffffffffu, s,  o);
            sq += __shfl_xor_sync(0xffffffffu, sq, o);
        }
        int wid = t >> 5, lid = t & 31;
        if (lid == 0) { red0[wid] = s; red1[wid] = sq; }
        __syncthreads();
        if (t == 0) {
            float S = 0.f, SQ = 0.f;
#pragma unroll
            for (int i = 0; i < 8; ++i) { S += red0[i]; SQ += red1[i]; }
            float mean = S * (1.0f/DIM);
            float var  = SQ * (1.0f/DIM) - mean*mean;
            mv[0] = mean; mv[1] = rsqrtf(var + EPSLN);
        }
        __syncthreads();
        float mean = mv[0], inv = mv[1];
        float* o = g_xnorm + (size_t)row*DIM;
        o[t]     = round_tf32f((v0-mean)*inv*gamma[t]     + beta[t]);
        o[t+256] = round_tf32f((v1-mean)*inv*gamma[t+256] + beta[t+256]);
        o[t+512] = round_tf32f((v2-mean)*inv*gamma[t+512] + beta[t+512]);
    }
}

// ---------------- chunk loader: A 128 rows (gathered) x 32 fl; B 32 x 96; NT=384 ----------------
__device__ __forceinline__ void load_chunk(const float* __restrict__ A, int lda,
                                           const float* __restrict__ B, int ldb,
                                           int n0, int k0,
                                           const int* __restrict__ rowidx,
                                           float* As, float* Bs) {
    int t = threadIdx.x;
#pragma unroll
    for (int i = 0; i < 3; ++i) {          // 1024 A cp16 over 384 threads
        int ci = t + i*NT;
        if (ci < 1024) {
            int row = ci >> 3, seg = ci & 7;
            cp16(smem_u32(As + row*ASTR + seg*4),
                 A + (size_t)rowidx[row]*lda + k0 + seg*4);
        }
    }
#pragma unroll
    for (int i = 0; i < 2; ++i) {          // 768 B cp16 over 384 threads
        int ci = t + i*NT;
        int k = ci / 24, c16 = ci % 24;
        cp16(smem_u32(Bs + k*BSTR + c16*4),
             B + (size_t)(k0+k)*ldb + n0 + c16*4);
    }
}

// ---------------- mma mainloop: 3-stage ring; 12 warps 4(M)x3(N), 32x32 each ----------------
__device__ __forceinline__ void mma_mainloop(const float* __restrict__ A, int lda,
                                             const float* __restrict__ B, int ldb,
                                             int K, int n0,
                                             const int* __restrict__ rowidx,
                                             float* smem, float acc[2][4][4]) {
    int t = threadIdx.x;
    int wid = t >> 5, lane = t & 31;
    int wm = wid & 3, wnn = wid >> 2;      // 4 M-rows x 3 N-cols of warps
    int qid = lane >> 2, qtr = lane & 3;

    int l8 = lane & 7, lhi = (lane >> 3) & 1, lk = lane >> 4;
    uint32_t a_off[2];
#pragma unroll
    for (int mt = 0; mt < 2; ++mt) {
        int row = wm*32 + mt*16 + lhi*8 + l8;
        a_off[mt] = (uint32_t)((row*ASTR + lk*4) * 4);
    }

    int nch = K / BK;
    load_chunk(A, lda, B, ldb, n0, 0,  rowidx, smem,           smem + ABUF);
    cp_commit();
    load_chunk(A, lda, B, ldb, n0, BK, rowidx, smem + STAGE,   smem + STAGE + ABUF);
    cp_commit();

    for (int c = 0; c < nch; ++c) {
        cp_wait1();
        __syncthreads();
        const float* Bb = smem + (c % NSTAGE)*STAGE + ABUF;
        uint32_t ab_base = smem_u32(smem + (c % NSTAGE)*STAGE);
#pragma unroll
        for (int ks = 0; ks < 4; ++ks) {
            int k0 = ks * 8;
            uint32_t af[2][4], bf[4][2];
#pragma unroll
            for (int mt = 0; mt < 2; ++mt)
                ldsm_x4(af[mt][0], af[mt][1], af[mt][2], af[mt][3],
                        ab_base + a_off[mt] + (uint32_t)(ks*32));
#pragma unroll
            for (int nt = 0; nt < 4; ++nt) {
                int cc = wnn*32 + nt*8 + qid;
                bf[nt][0] = __float_as_uint(Bb[(k0 + qtr    )*BSTR + cc]);
                bf[nt][1] = __float_as_uint(Bb[(k0 + qtr + 4)*BSTR + cc]);
            }
#pragma unroll
            for (int mt = 0; mt < 2; ++mt)
#pragma unroll
                for (int nt = 0; nt < 4; ++nt)
                    mma_tf32(acc[mt][nt][0], acc[mt][nt][1],
                             acc[mt][nt][2], acc[mt][nt][3],
                             af[mt][0], af[mt][1], af[mt][2], af[mt][3],
                             bf[nt][0], bf[nt][1]);
        }
        if (c + 2 < nch) {
            int st = (c + 2) % NSTAGE;
            load_chunk(A, lda, B, ldb, n0, (c+2)*BK, rowidx,
                       smem + st*STAGE, smem + st*STAGE + ABUF);
        }
        cp_commit();
    }
}

__device__ __forceinline__ float gelu_exact(float v) {
    return 0.5f * v * (1.0f + erff(v * 0.70710678118654752f));
}

// ---------------- main MLP GEMM1: h = round(gelu(xnorm @ W1 + b1)) ----------------
__global__ void __launch_bounds__(NT, 2) k_gemm1_main(const float* __restrict__ b1) {
    extern __shared__ float smem[];
    __shared__ int s_row[BM];
    int t = threadIdx.x;
    int m0 = blockIdx.y * BM, n0 = blockIdx.x * BN;
    if (t < BM) s_row[t] = m0 + t;
    __syncthreads();
    float acc[2][4][4] = {};
    mma_mainloop(g_xnorm, DIM, g_W1r, HID, DIM, n0, s_row, smem, acc);
    int wid = t >> 5, lane = t & 31;
    int wm = wid & 3, wnn = wid >> 2, qid = lane >> 2, qtr = lane & 3;
#pragma unroll
    for (int mt = 0; mt < 2; ++mt) {
        int r0 = m0 + wm*32 + mt*16 + qid;
#pragma unroll
        for (int nt = 0; nt < 4; ++nt) {
            int col = n0 + wnn*32 + nt*8 + qtr*2;
            float bx = b1[col], by = b1[col+1];
            *(float2*)(g_h + (size_t)r0*HID + col) =
                make_float2(round_tf32f(gelu_exact(acc[mt][nt][0]+bx)),
                            round_tf32f(gelu_exact(acc[mt][nt][1]+by)));
            *(float2*)(g_h + (size_t)(r0+8)*HID + col) =
                make_float2(round_tf32f(gelu_exact(acc[mt][nt][2]+bx)),
                            round_tf32f(gelu_exact(acc[mt][nt][3]+by)));
        }
    }
}

// ---------------- fused mid kernel: gemm2_main tiles + gemm1_adapt tiles ----------------
__global__ void __launch_bounds__(NT, 2) k_mid(const float* __restrict__ b2,
                                               const float* __restrict__ a1b) {
    extern __shared__ float smem[];
    __shared__ int s_row[BM];
    int t = threadIdx.x;
    int bid = blockIdx.x;
    int wid = t >> 5, lane = t & 31;
    int wm = wid & 3, wnn = wid >> 2, qid = lane >> 2, qtr = lane & 3;

    if (bid < MID_MAIN_BLKS) {
        // ---- main = g_h @ W2r + b2 ----
        int m0 = (bid / NDIM) * BM, n0 = (bid % NDIM) * BN;
        if (t < BM) s_row[t] = m0 + t;
        __syncthreads();
        float acc[2][4][4] = {};
        mma_mainloop(g_h, HID, g_W2r, DIM, HID, n0, s_row, smem, acc);
#pragma unroll
        for (int mt = 0; mt < 2; ++mt) {
            int r0 = m0 + wm*32 + mt*16 + qid;
#pragma unroll
            for (int nt = 0; nt < 4; ++nt) {
                int col = n0 + wnn*32 + nt*8 + qtr*2;
                float bx = b2[col], by = b2[col+1];
                *(float2*)(g_main + (size_t)r0*DIM + col) =
                    make_float2(acc[mt][nt][0]+bx, acc[mt][nt][1]+by);
                *(float2*)(g_main + (size_t)(r0+8)*DIM + col) =
                    make_float2(acc[mt][nt][2]+bx, acc[mt][nt][3]+by);
            }
        }
    } else {
        // ---- hl = round(relu(xnorm[perm] @ A1r[lvl] + a1b[lvl])) ----
        int b2i = bid - MID_MAIN_BLKS;
        int tile = b2i / NH2;
        if (tile >= g_ntiles) return;
        int n0 = (b2i % NH2) * BN;
        int lvl = g_sched_lvl[tile], start = g_sched_start[tile], rows = g_sched_rows[tile];
        if (t < BM) s_row[t] = g_rowperm[start + min(t, rows-1)];
        __syncthreads();
        float acc[2][4][4] = {};
        mma_mainloop(g_xnorm, DIM, g_A1r + (size_t)lvl*DIM*HID2, HID2, DIM, n0,
                     s_row, smem, acc);
        const float* bb = a1b + (size_t)lvl*HID2;
#pragma unroll
        for (int mt = 0; mt < 2; ++mt) {
            int ml = wm*32 + mt*16 + qid;
#pragma unroll
            for (int nt = 0; nt < 4; ++nt) {
                int col = n0 + wnn*32 + nt*8 + qtr*2;
                float bx = bb[col], by = bb[col+1];
                if (ml < rows)
                    *(float2*)(g_hl + (size_t)(start+ml)*HID2 + col) =
                        make_float2(round_tf32f(fmaxf(acc[mt][nt][0]+bx, 0.f)),
                                    round_tf32f(fmaxf(acc[mt][nt][1]+by, 0.f)));
                if (ml+8 < rows)
                    *(float2*)(g_hl + (size_t)(start+ml+8)*HID2 + col) =
                        make_float2(round_tf32f(fmaxf(acc[mt][nt][2]+bx, 0.f)),
                                    round_tf32f(fmaxf(acc[mt][nt][3]+by, 0.f)));
            }
        }
    }
}

// ---------------- adapter GEMM2 + final combine ----------------
__global__ void __launch_bounds__(NT, 2) k_gemm2_adapt(const float* __restrict__ a2b,
                                                       float* __restrict__ out) {
    if ((int)blockIdx.y >= g_ntiles) return;
    extern __shared__ float smem[];
    __shared__ int s_row[BM];
    int t = threadIdx.x;
    int tile = blockIdx.y;
    int lvl = g_sched_lvl[tile], start = g_sched_start[tile], rows = g_sched_rows[tile];
    int n0 = blockIdx.x * BN;
    if (t < BM) s_row[t] = min(start + t, MROWS-1);   // g_hl rows are compacted
    __syncthreads();
    float acc[2][4][4] = {};
    mma_mainloop(g_hl, HID2, g_A2r + (size_t)lvl*HID2*DIM, DIM, HID2, n0, s_row, smem, acc);
    int wid = t >> 5, lane = t & 31;
    int wm = wid & 3, wnn = wid >> 2, qid = lane >> 2, qtr = lane & 3;
    const float* bb = a2b + (size_t)lvl*DIM;
#pragma unroll
    for (int mt = 0; mt < 2; ++mt) {
        int ml = wm*32 + mt*16 + qid;
#pragma unroll
        for (int nt = 0; nt < 4; ++nt) {
            int col = n0 + wnn*32 + nt*8 + qtr*2;
            float bx = bb[col], by = bb[col+1];
            if (ml < rows) {
                int r = g_rowperm[start + ml];
                float mix = g_mix[r & (SEQ-1)];
                const float* mp = g_main + (size_t)r*DIM + col;
                *(float2*)(out + (size_t)r*DIM + col) =
                    make_float2(mp[0]*(1.f-mix) + (acc[mt][nt][0]+bx)*mix,
                                mp[1]*(1.f-mix) + (acc[mt][nt][1]+by)*mix);
            }
            if (ml+8 < rows) {
                int r = g_rowperm[start + ml + 8];
                float mix = g_mix[r & (SEQ-1)];
                const float* mp = g_main + (size_t)r*DIM + col;
                *(float2*)(out + (size_t)r*DIM + col) =
                    make_float2(mp[0]*(1.f-mix) + (acc[mt][nt][2]+bx)*mix,
                                mp[1]*(1.f-mix) + (acc[mt][nt][3]+by)*mix);
            }
        }
    }
}

// ---------------- launch ----------------
extern "C" void kernel_launch(void* const* d_in, const int* in_sizes, int n_in,
                              void* d_out, int out_size) {
    const float* x      = (const float*)d_in[0];
    const int*   levels = (const int*)  d_in[1];
    const float* gamma  = (const float*)d_in[2];
    const float* beta   = (const float*)d_in[3];
    const float* W1     = (const float*)d_in[4];
    const float* b1     = (const float*)d_in[5];
    const float* W2     = (const float*)d_in[6];
    const float* b2     = (const float*)d_in[7];
    const float* A1     = (const float*)d_in[8];
    const float* a1b    = (const float*)d_in[9];
    const float* A2     = (const float*)d_in[10];
    const float* a2b    = (const float*)d_in[11];
    const float* lmw    = (const float*)d_in[12];
    float* out = (float*)d_out;

    cudaFuncSetAttribute(k_gemm1_main,  cudaFuncAttributeMaxDynamicSharedMemorySize, SMEM_BYTES);
    cudaFuncSetAttribute(k_mid,         cudaFuncAttributeMaxDynamicSharedMemorySize, SMEM_BYTES);
    cudaFuncSetAttribute(k_gemm2_adapt, cudaFuncAttributeMaxDynamicSharedMemorySize, SMEM_BYTES);

    k_prep_all<<<NB_PREP_ALL, 256>>>((const float4*)W1, (const float4*)W2,
                                     (const float4*)A1, (const float4*)A2,
                                     levels, lmw, x, gamma, beta);
    k_gemm1_main <<<dim3(NMAIN, MROWS/BM), NT, SMEM_BYTES>>>(b1);
    k_mid        <<<MID_BLKS, NT, SMEM_BYTES>>>(b2, a1b);
    k_gemm2_adapt<<<dim3(NDIM, MAX_TILES), NT, SMEM_BYTES>>>(a2b, out);
}

// round 13
// speedup vs baseline: 4.2053x; 1.4733x over previous
#include <cuda_runtime.h>
#include <cuda_fp16.h>
#include <cstdint>
#include <math.h>

#define DIM   768
#define HID   3072
#define HID2  1536
#define NLEV  9
#define SEQ   2048
#define MROWS 4096
#define EPSLN 1e-5f

#define BM 128
#define BN 96
#define BK 32
#define NT 384
#define MAX_TILES 48

#define ASTRH 40    /* A smem row stride in halves (80B): 16B aligned, 8-row bank-bijective */
#define BSTRH 104   /* B smem row stride in halves (208B): 96 data + 8 pad */
#define ABUFH (BM*ASTRH)   /* 5120 halves */
#define BBUFH (BK*BSTRH)   /* 3328 halves */
#define STAGEH (ABUFH+BBUFH)          /* 8448 halves = 16896 B */
#define NSTAGE 3
#define SMEM_BYTES (NSTAGE*STAGEH*2)  /* 50688 B */

#define NMAIN (HID/BN)    /* 32 */
#define NDIM  (DIM/BN)    /* 8 */
#define NH2   (HID2/BN)   /* 16 */
#define MID_MAIN_BLKS (NDIM*32)   /* 256 */
#define MID_BLKS (MID_MAIN_BLKS + NH2*MAX_TILES)

// ---------------- scratch (no allocations allowed) ----------------
__device__ __half g_xnorm[MROWS*DIM];
__device__ __half g_h[(size_t)MROWS*HID];
__device__ float  g_main[MROWS*DIM];
__device__ __half g_hl[MROWS*HID2];
__device__ __half g_W1h[DIM*HID];
__device__ __half g_W2h[HID*DIM];
__device__ __half g_A1h[NLEV*DIM*HID2];
__device__ __half g_A2h[NLEV*HID2*DIM];
__device__ float g_mix[SEQ];
__device__ int   g_depth[SEQ];
__device__ int   g_rowperm[MROWS];
__device__ int   g_sched_lvl[MAX_TILES];
__device__ int   g_sched_start[MAX_TILES];
__device__ int   g_sched_rows[MAX_TILES];
__device__ int   g_ntiles;

// ---------------- PTX helpers ----------------
__device__ __forceinline__ uint32_t smem_u32(const void* p) {
    return (uint32_t)__cvta_generic_to_shared(p);
}
__device__ __forceinline__ void cp16(uint32_t dst, const void* src) {
    asm volatile("cp.async.cg.shared.global [%0], [%1], 16;" :: "r"(dst), "l"(src));
}
__device__ __forceinline__ void cp_commit() {
    asm volatile("cp.async.commit_group;" ::: "memory");
}
__device__ __forceinline__ void cp_wait1() {
    asm volatile("cp.async.wait_group 1;" ::: "memory");
}
__device__ __forceinline__ void ldsm_x4(uint32_t& r0, uint32_t& r1, uint32_t& r2, uint32_t& r3,
                                        uint32_t addr) {
    asm volatile("ldmatrix.sync.aligned.m8n8.x4.shared.b16 {%0,%1,%2,%3}, [%4];"
                 : "=r"(r0), "=r"(r1), "=r"(r2), "=r"(r3) : "r"(addr));
}
__device__ __forceinline__ void ldsm_x4_t(uint32_t& r0, uint32_t& r1, uint32_t& r2, uint32_t& r3,
                                          uint32_t addr) {
    asm volatile("ldmatrix.sync.aligned.m8n8.x4.trans.shared.b16 {%0,%1,%2,%3}, [%4];"
                 : "=r"(r0), "=r"(r1), "=r"(r2), "=r"(r3) : "r"(addr));
}
__device__ __forceinline__ void mma_fp16(float& c0, float& c1, float& c2, float& c3,
                                         uint32_t a0, uint32_t a1, uint32_t a2, uint32_t a3,
                                         uint32_t b0, uint32_t b1) {
    asm volatile(
        "mma.sync.aligned.m16n8k16.row.col.f32.f16.f16.f32 "
        "{%0,%1,%2,%3}, {%4,%5,%6,%7}, {%8,%9}, {%0,%1,%2,%3};"
        : "+f"(c0), "+f"(c1), "+f"(c2), "+f"(c3)
        : "r"(a0), "r"(a1), "r"(a2), "r"(a3), "r"(b0), "r"(b1));
}

// ---------------- fused prep: weight fp16 convert + schedule + layernorm ----------------
#define N4_W (DIM*HID/4)
#define N4_A (NLEV*DIM*HID2/4)
#define N4_TOTAL (2*N4_W + 2*N4_A)
#define NB_ROUND ((N4_TOTAL+255)/256)
#define NB_PREP_ALL (NB_ROUND + 1 + MROWS)

__global__ void __launch_bounds__(256) k_prep_all(
        const float4* __restrict__ W1, const float4* __restrict__ W2,
        const float4* __restrict__ A1, const float4* __restrict__ A2,
        const int* __restrict__ levels, const float* __restrict__ lmw,
        const float* __restrict__ x, const float* __restrict__ gamma,
        const float* __restrict__ beta) {
    int b = blockIdx.x;
    int t = threadIdx.x;
    if (b < NB_ROUND) {
        int i = b*256 + t;
        if (i >= N4_TOTAL) return;
        const float4* src; __half* dst;
        if (i < N4_W)            { src = W1 + i;                 dst = g_W1h + 4*(size_t)i; }
        else if (i < 2*N4_W)     { src = W2 + (i - N4_W);        dst = g_W2h + 4*(size_t)(i - N4_W); }
        else if (i < 2*N4_W+N4_A){ src = A1 + (i - 2*N4_W);      dst = g_A1h + 4*(size_t)(i - 2*N4_W); }
        else                     { src = A2 + (i - 2*N4_W-N4_A); dst = g_A2h + 4*(size_t)(i - 2*N4_W-N4_A); }
        float4 v = *src;
        __half2 lo = __floats2half2_rn(v.x, v.y);
        __half2 hi = __floats2half2_rn(v.z, v.w);
        uint2 pk = make_uint2(*(uint32_t*)&lo, *(uint32_t*)&hi);
        *(uint2*)dst = pk;
    } else if (b == NB_ROUND) {
        __shared__ int cnt[NLEV];
        __shared__ int cursor[NLEV];
        __shared__ float denom_sh;
        if (t < NLEV) cnt[t] = 0;
        __syncthreads();
        for (int s = t; s < SEQ; s += 256) {
            int d = levels[s*4];
            d = min(max(d, 0), NLEV-1);
            g_depth[s] = d;
            atomicAdd(&cnt[d], 1);
        }
        __syncthreads();
        if (t == 0) {
            int o = 0, tile = 0;
            float denom = 0.f;
            for (int l = 0; l < NLEV; ++l) {
                cursor[l] = o;
                int rows = 2*cnt[l];
                int nt2 = (rows + BM - 1)/BM;
                for (int i = 0; i < nt2 && tile < MAX_TILES; ++i) {
                    g_sched_lvl[tile]   = l;
                    g_sched_start[tile] = o + i*BM;
                    g_sched_rows[tile]  = min(BM, rows - i*BM);
                    ++tile;
                }
                o += rows;
                denom += (float)cnt[l] * expf(lmw[l]);
            }
            for (int i = tile; i < MAX_TILES; ++i) g_sched_rows[i] = 0;
            g_ntiles = tile;
            denom_sh = denom;
        }
        __syncthreads();
        for (int r = t; r < MROWS; r += 256) {
            int s = r & (SEQ-1);
            int d = g_depth[s];
            int pos = atomicAdd(&cursor[d], 1);
            g_rowperm[pos] = r;
        }
        float denom = denom_sh;
        for (int s = t; s < SEQ; s += 256)
            g_mix[s] = expf(lmw[g_depth[s]]) / denom;
    } else {
        int row = b - NB_ROUND - 1;
        const float* xr = x + (size_t)row*DIM;
        float v0 = xr[t], v1 = xr[t+256], v2 = xr[t+512];
        float s  = v0+v1+v2;
        float sq = v0*v0 + v1*v1 + v2*v2;
        __shared__ float red0[8], red1[8], mv[2];
#pragma unroll
        for (int o = 16; o > 0; o >>= 1) {
            s  += __shfl_xor_sync(0xffffffffu, s,  o);
            sq += __shfl_xor_sync(0xffffffffu, sq, o);
        }
        int wid = t >> 5, lid = t & 31;
        if (lid == 0) { red0[wid] = s; red1[wid] = sq; }
        __syncthreads();
        if (t == 0) {
            float S = 0.f, SQ = 0.f;
#pragma unroll
            for (int i = 0; i < 8; ++i) { S += red0[i]; SQ += red1[i]; }
            float mean = S * (1.0f/DIM);
            float var  = SQ * (1.0f/DIM) - mean*mean;
            mv[0] = mean; mv[1] = rsqrtf(var + EPSLN);
        }
        __syncthreads();
        float mean = mv[0], inv = mv[1];
        __half* o = g_xnorm + (size_t)row*DIM;
        o[t]     = __float2half_rn((v0-mean)*inv*gamma[t]     + beta[t]);
        o[t+256] = __float2half_rn((v1-mean)*inv*gamma[t+256] + beta[t+256]);
        o[t+512] = __float2half_rn((v2-mean)*inv*gamma[t+512] + beta[t+512]);
    }
}

// ---------------- chunk loader: A 128 rows (gathered) x 32 halves; B 32 x 96 halves ----------------
__device__ __forceinline__ void load_chunk(const __half* __restrict__ A, int lda,
                                           const __half* __restrict__ B, int ldb,
                                           int n0, int k0,
                                           const int* __restrict__ rowidx,
                                           __half* As, __half* Bs) {
    int t = threadIdx.x;
    // A: 512 cp16 (128 rows x 4 segs of 8 halves)
#pragma unroll
    for (int i = 0; i < 2; ++i) {
        int ci = t + i*NT;
        if (ci < 512) {
            int row = ci >> 2, seg = ci & 3;
            cp16(smem_u32(As + row*ASTRH + seg*8),
                 A + (size_t)rowidx[row]*lda + k0 + seg*8);
        }
    }
    // B: 384 cp16 (32 k-rows x 12 segs of 8 halves)
    {
        int k = t / 12, c16 = t % 12;
        cp16(smem_u32(Bs + k*BSTRH + c16*8),
             B + (size_t)(k0+k)*ldb + n0 + c16*8);
    }
}

// ---------------- mma mainloop: 3-stage ring; 12 warps 4(M)x3(N); fp16 m16n8k16 ----------------
__device__ __forceinline__ void mma_mainloop(const __half* __restrict__ A, int lda,
                                             const __half* __restrict__ B, int ldb,
                                             int K, int n0,
                                             const int* __restrict__ rowidx,
                                             __half* smem, float acc[2][4][4]) {
    int t = threadIdx.x;
    int wid = t >> 5, lane = t & 31;
    int wm = wid & 3, wnn = wid >> 2;      // 4 M-warps x 3 N-warps
    int l8 = lane & 7, lhi = (lane >> 3) & 1, lch = lane >> 4;

    // A ldmatrix addresses: 16x16 half tile per mt
    uint32_t a_off[2];
#pragma unroll
    for (int mt = 0; mt < 2; ++mt) {
        int row = wm*32 + mt*16 + lhi*8 + l8;
        a_off[mt] = (uint32_t)((row*ASTRH + lch*8) * 2);
    }
    // B ldmatrix.trans addresses: k16 x n16 tile per np
    uint32_t b_off[2];
#pragma unroll
    for (int np = 0; np < 2; ++np) {
        int k = lhi*8 + l8;
        int n = wnn*32 + np*16 + lch*8;
        b_off[np] = (uint32_t)(ABUFH*2 + (k*BSTRH + n) * 2);
    }

    int nch = K / BK;
    load_chunk(A, lda, B, ldb, n0, 0,  rowidx, smem,            smem + ABUFH);
    cp_commit();
    load_chunk(A, lda, B, ldb, n0, BK, rowidx, smem + STAGEH,   smem + STAGEH + ABUFH);
    cp_commit();

    for (int c = 0; c < nch; ++c) {
        cp_wait1();
        __syncthreads();
        uint32_t st_base = smem_u32(smem + (c % NSTAGE)*STAGEH);
#pragma unroll
        for (int ks = 0; ks < 2; ++ks) {          // 2 k-steps of 16
            uint32_t af[2][4], bf[4][2];
#pragma unroll
            for (int mt = 0; mt < 2; ++mt)
                ldsm_x4(af[mt][0], af[mt][1], af[mt][2], af[mt][3],
                        st_base + a_off[mt] + (uint32_t)(ks*32));      // 16 halves = 32B
#pragma unroll
            for (int np = 0; np < 2; ++np)
                ldsm_x4_t(bf[2*np][0], bf[2*np][1], bf[2*np+1][0], bf[2*np+1][1],
                          st_base + b_off[np] + (uint32_t)(ks*16*BSTRH*2));
#pragma unroll
            for (int mt = 0; mt < 2; ++mt)
#pragma unroll
                for (int nt = 0; nt < 4; ++nt)
                    mma_fp16(acc[mt][nt][0], acc[mt][nt][1],
                             acc[mt][nt][2], acc[mt][nt][3],
                             af[mt][0], af[mt][1], af[mt][2], af[mt][3],
                             bf[nt][0], bf[nt][1]);
        }
        if (c + 2 < nch) {
            int st = (c + 2) % NSTAGE;
            load_chunk(A, lda, B, ldb, n0, (c+2)*BK, rowidx,
                       smem + st*STAGEH, smem + st*STAGEH + ABUFH);
        }
        cp_commit();
    }
}

__device__ __forceinline__ float gelu_exact(float v) {
    return 0.5f * v * (1.0f + erff(v * 0.70710678118654752f));
}
__device__ __forceinline__ void st_h2(__half* p, float a, float b) {
    *(__half2*)p = __floats2half2_rn(a, b);
}

// ---------------- main MLP GEMM1: h = fp16(gelu(xnorm @ W1 + b1)) ----------------
__global__ void __launch_bounds__(NT, 2) k_gemm1_main(const float* __restrict__ b1) {
    extern __shared__ __half smem[];
    __shared__ int s_row[BM];
    int t = threadIdx.x;
    int m0 = blockIdx.y * BM, n0 = blockIdx.x * BN;
    if (t < BM) s_row[t] = m0 + t;
    __syncthreads();
    float acc[2][4][4] = {};
    mma_mainloop(g_xnorm, DIM, g_W1h, HID, DIM, n0, s_row, smem, acc);
    int wid = t >> 5, lane = t & 31;
    int wm = wid & 3, wnn = wid >> 2, qid = lane >> 2, qtr = lane & 3;
#pragma unroll
    for (int mt = 0; mt < 2; ++mt) {
        int r0 = m0 + wm*32 + mt*16 + qid;
#pragma unroll
        for (int nt = 0; nt < 4; ++nt) {
            int col = n0 + wnn*32 + nt*8 + qtr*2;
            float bx = b1[col], by = b1[col+1];
            st_h2(g_h + (size_t)r0*HID + col,
                  gelu_exact(acc[mt][nt][0]+bx), gelu_exact(acc[mt][nt][1]+by));
            st_h2(g_h + (size_t)(r0+8)*HID + col,
                  gelu_exact(acc[mt][nt][2]+bx), gelu_exact(acc[mt][nt][3]+by));
        }
    }
}

// ---------------- fused mid kernel: gemm2_main tiles + gemm1_adapt tiles ----------------
__global__ void __launch_bounds__(NT, 2) k_mid(const float* __restrict__ b2,
                                               const float* __restrict__ a1b) {
    extern __shared__ __half smem[];
    __shared__ int s_row[BM];
    int t = threadIdx.x;
    int bid = blockIdx.x;
    int wid = t >> 5, lane = t & 31;
    int wm = wid & 3, wnn = wid >> 2, qid = lane >> 2, qtr = lane & 3;

    if (bid < MID_MAIN_BLKS) {
        // ---- main = g_h @ W2 + b2 (fp32 out) ----
        int m0 = (bid / NDIM) * BM, n0 = (bid % NDIM) * BN;
        if (t < BM) s_row[t] = m0 + t;
        __syncthreads();
        float acc[2][4][4] = {};
        mma_mainloop(g_h, HID, g_W2h, DIM, HID, n0, s_row, smem, acc);
#pragma unroll
        for (int mt = 0; mt < 2; ++mt) {
            int r0 = m0 + wm*32 + mt*16 + qid;
#pragma unroll
            for (int nt = 0; nt < 4; ++nt) {
                int col = n0 + wnn*32 + nt*8 + qtr*2;
                float bx = b2[col], by = b2[col+1];
                *(float2*)(g_main + (size_t)r0*DIM + col) =
                    make_float2(acc[mt][nt][0]+bx, acc[mt][nt][1]+by);
                *(float2*)(g_main + (size_t)(r0+8)*DIM + col) =
                    make_float2(acc[mt][nt][2]+bx, acc[mt][nt][3]+by);
            }
        }
    } else {
        // ---- hl = fp16(relu(xnorm[perm] @ A1[lvl] + a1b[lvl])) ----
        int b2i = bid - MID_MAIN_BLKS;
        int tile = b2i / NH2;
        if (tile >= g_ntiles) return;
        int n0 = (b2i % NH2) * BN;
        int lvl = g_sched_lvl[tile], start = g_sched_start[tile], rows = g_sched_rows[tile];
        if (t < BM) s_row[t] = g_rowperm[start + min(t, rows-1)];
        __syncthreads();
        float acc[2][4][4] = {};
        mma_mainloop(g_xnorm, DIM, g_A1h + (size_t)lvl*DIM*HID2, HID2, DIM, n0,
                     s_row, smem, acc);
        const float* bb = a1b + (size_t)lvl*HID2;
#pragma unroll
        for (int mt = 0; mt < 2; ++mt) {
            int ml = wm*32 + mt*16 + qid;
#pragma unroll
            for (int nt = 0; nt < 4; ++nt) {
                int col = n0 + wnn*32 + nt*8 + qtr*2;
                float bx = bb[col], by = bb[col+1];
                if (ml < rows)
                    st_h2(g_hl + (size_t)(start+ml)*HID2 + col,
                          fmaxf(acc[mt][nt][0]+bx, 0.f), fmaxf(acc[mt][nt][1]+by, 0.f));
                if (ml+8 < rows)
                    st_h2(g_hl + (size_t)(start+ml+8)*HID2 + col,
                          fmaxf(acc[mt][nt][2]+bx, 0.f), fmaxf(acc[mt][nt][3]+by, 0.f));
            }
        }
    }
}

// ---------------- adapter GEMM2 + final combine ----------------
__global__ void __launch_bounds__(NT, 2) k_gemm2_adapt(const float* __restrict__ a2b,
                                                       float* __restrict__ out) {
    if ((int)blockIdx.y >= g_ntiles) return;
    extern __shared__ __half smem[];
    __shared__ int s_row[BM];
    int t = threadIdx.x;
    int tile = blockIdx.y;
    int lvl = g_sched_lvl[tile], start = g_sched_start[tile], rows = g_sched_rows[tile];
    int n0 = blockIdx.x * BN;
    if (t < BM) s_row[t] = min(start + t, MROWS-1);   // g_hl rows are compacted
    __syncthreads();
    float acc[2][4][4] = {};
    mma_mainloop(g_hl, HID2, g_A2h + (size_t)lvl*HID2*DIM, DIM, HID2, n0, s_row, smem, acc);
    int wid = t >> 5, lane = t & 31;
    int wm = wid & 3, wnn = wid >> 2, qid = lane >> 2, qtr = lane & 3;
    const float* bb = a2b + (size_t)lvl*DIM;
#pragma unroll
    for (int mt = 0; mt < 2; ++mt) {
        int ml = wm*32 + mt*16 + qid;
#pragma unroll
        for (int nt = 0; nt < 4; ++nt) {
            int col = n0 + wnn*32 + nt*8 + qtr*2;
            float bx = bb[col], by = bb[col+1];
            if (ml < rows) {
                int r = g_rowperm[start + ml];
                float mix = g_mix[r & (SEQ-1)];
                const float* mp = g_main + (size_t)r*DIM + col;
                *(float2*)(out + (size_t)r*DIM + col) =
                    make_float2(mp[0]*(1.f-mix) + (acc[mt][nt][0]+bx)*mix,
                                mp[1]*(1.f-mix) + (acc[mt][nt][1]+by)*mix);
            }
            if (ml+8 < rows) {
                int r = g_rowperm[start + ml + 8];
                float mix = g_mix[r & (SEQ-1)];
                const float* mp = g_main + (size_t)r*DIM + col;
                *(float2*)(out + (size_t)r*DIM + col) =
                    make_float2(mp[0]*(1.f-mix) + (acc[mt][nt][2]+bx)*mix,
                                mp[1]*(1.f-mix) + (acc[mt][nt][3]+by)*mix);
            }
        }
    }
}

// ---------------- launch ----------------
extern "C" void kernel_launch(void* const* d_in, const int* in_sizes, int n_in,
                              void* d_out, int out_size) {
    const float* x      = (const float*)d_in[0];
    const int*   levels = (const int*)  d_in[1];
    const float* gamma  = (const float*)d_in[2];
    const float* beta   = (const float*)d_in[3];
    const float* W1     = (const float*)d_in[4];
    const float* b1     = (const float*)d_in[5];
    const float* W2     = (const float*)d_in[6];
    const float* b2     = (const float*)d_in[7];
    const float* A1     = (const float*)d_in[8];
    const float* a1b    = (const float*)d_in[9];
    const float* A2     = (const float*)d_in[10];
    const float* a2b    = (const float*)d_in[11];
    const float* lmw    = (const float*)d_in[12];
    float* out = (float*)d_out;

    cudaFuncSetAttribute(k_gemm1_main,  cudaFuncAttributeMaxDynamicSharedMemorySize, SMEM_BYTES);
    cudaFuncSetAttribute(k_mid,         cudaFuncAttributeMaxDynamicSharedMemorySize, SMEM_BYTES);
    cudaFuncSetAttribute(k_gemm2_adapt, cudaFuncAttributeMaxDynamicSharedMemorySize, SMEM_BYTES);

    k_prep_all<<<NB_PREP_ALL, 256>>>((const float4*)W1, (const float4*)W2,
                                     (const float4*)A1, (const float4*)A2,
                                     levels, lmw, x, gamma, beta);
    k_gemm1_main <<<dim3(NMAIN, MROWS/BM), NT, SMEM_BYTES>>>(b1);
    k_mid        <<<MID_BLKS, NT, SMEM_BYTES>>>(b2, a1b);
    k_gemm2_adapt<<<dim3(NDIM, MAX_TILES), NT, SMEM_BYTES>>>(a2b, out);
}